// round 1
// baseline (speedup 1.0000x reference)
#include <cuda_runtime.h>
#include <math.h>

// ---------------------------------------------------------------------------
// Scratch pool (single __device__ global; allocation-free per harness rules)
// ---------------------------------------------------------------------------
static constexpr long PX = 512L * 512;   // 262144

static constexpr long O_S1    = 0;                         // (2,3,512,512)
static constexpr long O_S2    = O_S1    + 6 * PX;          // (2,3,256,256)
static constexpr long O_S3    = O_S2    + 6 * (PX / 4);    // (2,3,128,128)
static constexpr long O_S4    = O_S3    + 6 * (PX / 16);   // (2,3,64,64)
static constexpr long O_MULTI = O_S4    + 6 * (PX / 64);   // (2,12,512,512)
static constexpr long O_MS    = O_MULTI + 24 * PX;         // (2,16,512,512)
static constexpr long O_C2    = O_MS    + 32 * PX;         // (2,16,512,512)
static constexpr long O_C2P   = O_C2    + 32 * PX;         // (2,16,256,256)
static constexpr long O_C3    = O_C2P   + 32 * (PX / 4);   // (2,32,256,256)
static constexpr long O_C3P   = O_C3    + 64 * (PX / 4);   // (2,32,128,128)
static constexpr long O_C4    = O_C3P   + 64 * (PX / 16);  // (2,32,128,128)
static constexpr long O_C4P   = O_C4    + 64 * (PX / 16);  // (2,32,64,64)
static constexpr long O_C5    = O_C4P   + 64 * (PX / 64);  // (2,32,64,64)
static constexpr long O_C5P   = O_C5    + 64 * (PX / 64);  // (2,32,32,32)
static constexpr long O_C6    = O_C5P   + 64 * (PX / 256); // (2,64,32,32)
static constexpr long O_C6U   = O_C6    + 128 * (PX / 256);// (2,64,64,64)
static constexpr long O_C6S   = O_C6U   + 128 * (PX / 64); // (2,64,64,64)
static constexpr long O_C6RE  = O_C6S   + 128 * (PX / 64); // (2,64,128,128)
static constexpr long O_C7C   = O_C6RE  + 128 * (PX / 16); // (2,32,128,128)
static constexpr long O_C7    = O_C7C   + 64 * (PX / 16);  // (2,32,256,256)
static constexpr long O_C8C   = O_C7    + 64 * (PX / 4);   // (2,16,256,256)
static constexpr long O_C8    = O_C8C   + 32 * (PX / 4);   // (2,16,512,512)
static constexpr long O_C9    = O_C8    + 32 * PX;         // (2,64,512,512)
static constexpr long O_H1    = O_C9    + 128 * PX;        // (2,16,512,512)
static constexpr long O_H2    = O_H1    + 32 * PX;
static constexpr long O_H3    = O_H2    + 32 * PX;
static constexpr long O_H4    = O_H3    + 32 * PX;
static constexpr long O_HM    = O_H4    + 32 * PX;         // max(h5,h6)
static constexpr long O_ELT   = O_HM    + 32 * PX;         // final elt_max
static constexpr long O_C10   = O_ELT   + 32 * PX;         // (2,64,512,512)
static constexpr long POOL_TOTAL = O_C10 + 128 * PX;       // ~170.6M floats

__device__ float g_pool[POOL_TOTAL];

// ---------------------------------------------------------------------------
// Direct convolution, SAME padding, stride 1, NCHW, OIHW weights.
// Two concatenated input sources (srcB may be null, cb=0).
// Each thread computes 4 adjacent x outputs (register tiling).
// ACT: 0 = none, 1 = relu, 2 = tanh
// ---------------------------------------------------------------------------
template <int K, int ACT>
__global__ void conv2d_kernel(const float* __restrict__ srcA, int ca,
                              const float* __restrict__ srcB, int cb,
                              float* __restrict__ dst, int cout,
                              const float* __restrict__ w,
                              const float* __restrict__ bias,
                              int H, int W, int N)
{
    const int W4 = W >> 2;
    long idx = (long)blockIdx.x * blockDim.x + threadIdx.x;
    long total = (long)N * cout * H * W4;
    if (idx >= total) return;

    int x4 = (int)(idx % W4);  long t = idx / W4;
    int y  = (int)(t % H);     t /= H;
    int co = (int)(t % cout);
    int n  = (int)(t / cout);
    int x0 = x4 << 2;
    constexpr int P = K / 2;

    float bv = __ldg(bias + co);
    float a0 = bv, a1 = bv, a2 = bv, a3 = bv;

    const int ctot = ca + cb;
    const float* wbase = w + (long)co * ctot * (K * K);

    // x-validity is loop-invariant
    bool xok[K + 3];
#pragma unroll
    for (int i = 0; i < K + 3; ++i) {
        int xx = x0 - P + i;
        xok[i] = (xx >= 0 && xx < W);
    }

    for (int ci = 0; ci < ctot; ++ci) {
        const float* plane;
        if (ci < ca) plane = srcA + ((long)n * ca + ci) * H * W;
        else         plane = srcB + ((long)n * cb + (ci - ca)) * H * W;
        const float* wk = wbase + ci * (K * K);

#pragma unroll
        for (int ky = 0; ky < K; ++ky) {
            int yy = y + ky - P;
            if (yy < 0 || yy >= H) continue;
            const float* r = plane + (long)yy * W + (x0 - P);
            float v[K + 3];
#pragma unroll
            for (int i = 0; i < K + 3; ++i)
                v[i] = xok[i] ? __ldg(r + i) : 0.0f;
#pragma unroll
            for (int kx = 0; kx < K; ++kx) {
                float ww = __ldg(wk + ky * K + kx);
                a0 = fmaf(ww, v[kx + 0], a0);
                a1 = fmaf(ww, v[kx + 1], a1);
                a2 = fmaf(ww, v[kx + 2], a2);
                a3 = fmaf(ww, v[kx + 3], a3);
            }
        }
    }

    if (ACT == 1) {
        a0 = fmaxf(a0, 0.f); a1 = fmaxf(a1, 0.f);
        a2 = fmaxf(a2, 0.f); a3 = fmaxf(a3, 0.f);
    } else if (ACT == 2) {
        a0 = tanhf(a0); a1 = tanhf(a1); a2 = tanhf(a2); a3 = tanhf(a3);
    }

    long o = (((long)n * cout + co) * H + y) * W + x0;
    float4 o4 = make_float4(a0, a1, a2, a3);
    *reinterpret_cast<float4*>(dst + o) = o4;
}

// ---------------------------------------------------------------------------
// 2x2 max pool, stride 2
// ---------------------------------------------------------------------------
__global__ void maxpool_kernel(const float* __restrict__ src, float* __restrict__ dst,
                               int C, int Ho, int Wo, int N)
{
    long idx = (long)blockIdx.x * blockDim.x + threadIdx.x;
    long total = (long)N * C * Ho * Wo;
    if (idx >= total) return;
    int x = (int)(idx % Wo);  long t = idx / Wo;
    int y = (int)(t % Ho);    t /= Ho;
    int c = (int)(t % C);
    int n = (int)(t / C);
    int Hi = Ho * 2, Wi = Wo * 2;
    const float* p = src + (((long)n * C + c) * Hi + 2 * y) * Wi + 2 * x;
    float m = fmaxf(fmaxf(p[0], p[1]), fmaxf(p[Wi], p[Wi + 1]));
    dst[idx] = m;
}

// ---------------------------------------------------------------------------
// Bilinear upsample by integer scale (half-pixel centers, clamped = identical
// to jax.image.resize 'bilinear' boundary renormalization). scale=1 == copy.
// Separate batch strides so we can write directly into the `multi` concat.
// ---------------------------------------------------------------------------
__global__ void upsample_kernel(const float* __restrict__ src, float* __restrict__ dst,
                                int C, int Hs, int Ws, int scale,
                                long sBS, long dBS, int N)
{
    int Hd = Hs * scale, Wd = Ws * scale;
    long idx = (long)blockIdx.x * blockDim.x + threadIdx.x;
    long total = (long)N * C * Hd * Wd;
    if (idx >= total) return;
    int x = (int)(idx % Wd);  long t = idx / Wd;
    int y = (int)(t % Hd);    t /= Hd;
    int c = (int)(t % C);
    int n = (int)(t / C);

    float inv = 1.0f / (float)scale;
    float fy = (y + 0.5f) * inv - 0.5f;
    float fx = (x + 0.5f) * inv - 0.5f;
    int y0 = (int)floorf(fy);
    int x0 = (int)floorf(fx);
    float wy = fy - (float)y0;
    float wx = fx - (float)x0;
    int y0c = min(max(y0, 0), Hs - 1);
    int y1c = min(max(y0 + 1, 0), Hs - 1);
    int x0c = min(max(x0, 0), Ws - 1);
    int x1c = min(max(x0 + 1, 0), Ws - 1);

    const float* p = src + n * sBS + (long)c * Hs * Ws;
    float v00 = p[(long)y0c * Ws + x0c];
    float v01 = p[(long)y0c * Ws + x1c];
    float v10 = p[(long)y1c * Ws + x0c];
    float v11 = p[(long)y1c * Ws + x1c];
    float v = (1.f - wy) * ((1.f - wx) * v00 + wx * v01)
            +        wy  * ((1.f - wx) * v10 + wx * v11);

    dst[n * dBS + ((long)c * Hd + y) * Wd + x] = v;
}

// ---------------------------------------------------------------------------
// Linear recurrent scans. c9 channel map: gx1=0..15, gy1=16..31, gx2=32..47,
// gy2=48..63.  y_t = a_t * y_{t-1} + (1-a_t) * u_t, y_{-1} = 0.
// ---------------------------------------------------------------------------
__global__ void hscan12_kernel()   // h1 = scan(gx1, ms, x); h2 = scan(gx1, ms_revx, x)
{
    int idx = blockIdx.x * blockDim.x + threadIdx.x;
    if (idx >= 2 * 16 * 512) return;
    int y = idx % 512;  int t = idx / 512;
    int c = t % 16;     int n = t / 16;
    long rp = (((long)n * 16 + c) * 512 + y) * 512;
    const float* a  = g_pool + O_C9 + (((long)n * 64 + c) * 512 + y) * 512;
    const float* u  = g_pool + O_MS + rp;
    float* h1 = g_pool + O_H1 + rp;
    float* h2 = g_pool + O_H2 + rp;
    float y1 = 0.f, y2 = 0.f;
    for (int x = 0; x < 512; ++x) {
        float av = a[x];
        float om = 1.f - av;
        y1 = fmaf(av, y1, om * u[x]);
        y2 = fmaf(av, y2, om * u[511 - x]);
        h1[x] = y1;
        h2[x] = y2;
    }
}

__global__ void hscan56_kernel()   // hm = max(scan(gx2,h1,x), scan(gx2,h2_revx,x))
{
    int idx = blockIdx.x * blockDim.x + threadIdx.x;
    if (idx >= 2 * 16 * 512) return;
    int y = idx % 512;  int t = idx / 512;
    int c = t % 16;     int n = t / 16;
    long rp = (((long)n * 16 + c) * 512 + y) * 512;
    const float* a  = g_pool + O_C9 + (((long)n * 64 + 32 + c) * 512 + y) * 512;
    const float* h1 = g_pool + O_H1 + rp;
    const float* h2 = g_pool + O_H2 + rp;
    float* hm = g_pool + O_HM + rp;
    float y5 = 0.f, y6 = 0.f;
    for (int x = 0; x < 512; ++x) {
        float av = a[x];
        float om = 1.f - av;
        y5 = fmaf(av, y5, om * h1[x]);
        y6 = fmaf(av, y6, om * h2[511 - x]);
        hm[x] = fmaxf(y5, y6);
    }
}

__global__ void vscan34_kernel()   // h3 = scan(gate_v, ms, y); h4 = scan(gate_v, ms_revy, y)
{
    int idx = blockIdx.x * blockDim.x + threadIdx.x;
    if (idx >= 2 * 16 * 512) return;
    int x = idx % 512;  int t = idx / 512;
    int c = t % 16;     int n = t / 16;
    long pp = ((long)n * 16 + c) * 512 * 512;
    const float* gx1 = g_pool + O_C9 + ((long)n * 64 + c) * 512 * 512;
    const float* gy1 = g_pool + O_C9 + ((long)n * 64 + 16 + c) * 512 * 512; // row 0 used
    const float* u   = g_pool + O_MS + pp;
    float* h3 = g_pool + O_H3 + pp;
    float* h4 = g_pool + O_H4 + pp;
    float y3 = 0.f, y4 = 0.f;
    for (int ty = 0; ty < 512; ++ty) {
        float av = (ty == 0) ? gy1[x] : gx1[(long)ty * 512 + x];
        float om = 1.f - av;
        y3 = fmaf(av, y3, om * u[(long)ty * 512 + x]);
        y4 = fmaf(av, y4, om * u[(long)(511 - ty) * 512 + x]);
        h3[(long)ty * 512 + x] = y3;
        h4[(long)ty * 512 + x] = y4;
    }
}

__global__ void vscan78_kernel()   // elt = max(hm, scan(gy2,h3,y), scan(gy2,h4_revy,y))
{
    int idx = blockIdx.x * blockDim.x + threadIdx.x;
    if (idx >= 2 * 16 * 512) return;
    int x = idx % 512;  int t = idx / 512;
    int c = t % 16;     int n = t / 16;
    long pp = ((long)n * 16 + c) * 512 * 512;
    const float* a  = g_pool + O_C9 + ((long)n * 64 + 48 + c) * 512 * 512;
    const float* h3 = g_pool + O_H3 + pp;
    const float* h4 = g_pool + O_H4 + pp;
    const float* hm = g_pool + O_HM + pp;
    float* elt = g_pool + O_ELT + pp;
    float y7 = 0.f, y8 = 0.f;
    for (int ty = 0; ty < 512; ++ty) {
        float av = a[(long)ty * 512 + x];
        float om = 1.f - av;
        y7 = fmaf(av, y7, om * h3[(long)ty * 512 + x]);
        y8 = fmaf(av, y8, om * h4[(long)(511 - ty) * 512 + x]);
        elt[(long)ty * 512 + x] = fmaxf(hm[(long)ty * 512 + x], fmaxf(y7, y8));
    }
}

// ---------------------------------------------------------------------------
// Launch
// ---------------------------------------------------------------------------
static inline int gs(long total, int bs) { return (int)((total + bs - 1) / bs); }

extern "C" void kernel_launch(void* const* d_in, const int* in_sizes, int n_in,
                              void* d_out, int out_size)
{
    const float* x    = (const float*)d_in[0];
    const float* w_s1 = (const float*)d_in[1];  const float* b_s1 = (const float*)d_in[2];
    const float* w_mc = (const float*)d_in[3];  const float* b_mc = (const float*)d_in[4];
    const float* w2   = (const float*)d_in[5];  const float* b2   = (const float*)d_in[6];
    const float* w3   = (const float*)d_in[7];  const float* b3   = (const float*)d_in[8];
    const float* w4   = (const float*)d_in[9];  const float* b4   = (const float*)d_in[10];
    const float* w5   = (const float*)d_in[11]; const float* b5   = (const float*)d_in[12];
    const float* w6   = (const float*)d_in[13]; const float* b6   = (const float*)d_in[14];
    const float* w6s  = (const float*)d_in[15]; const float* b6s  = (const float*)d_in[16];
    const float* w7   = (const float*)d_in[17]; const float* b7   = (const float*)d_in[18];
    const float* w8   = (const float*)d_in[19]; const float* b8   = (const float*)d_in[20];
    const float* w9   = (const float*)d_in[21]; const float* b9   = (const float*)d_in[22];
    const float* w10  = (const float*)d_in[23]; const float* b10  = (const float*)d_in[24];
    const float* w11  = (const float*)d_in[25]; const float* b11  = (const float*)d_in[26];
    float* out = (float*)d_out;

    float* pool = nullptr;
    cudaGetSymbolAddress((void**)&pool, g_pool);

    const int BS = 256;
    const int N = 2;

    // s1 = conv3(x, 3->3), no act
    conv2d_kernel<3, 0><<<gs((long)N * 3 * 512 * 128, BS), BS>>>(
        x, 3, nullptr, 0, pool + O_S1, 3, w_s1, b_s1, 512, 512, N);
    // pyramid pools
    maxpool_kernel<<<gs((long)N * 3 * 256 * 256, BS), BS>>>(pool + O_S1, pool + O_S2, 3, 256, 256, N);
    maxpool_kernel<<<gs((long)N * 3 * 128 * 128, BS), BS>>>(pool + O_S2, pool + O_S3, 3, 128, 128, N);
    maxpool_kernel<<<gs((long)N * 3 * 64 * 64, BS), BS>>>(pool + O_S3, pool + O_S4, 3, 64, 64, N);

    // multi = concat([s1, up2(s2), up4(s3), up8(s4)]) -> (2,12,512,512)
    upsample_kernel<<<gs((long)N * 3 * PX, BS), BS>>>(pool + O_S1, pool + O_MULTI + 0 * PX,
        3, 512, 512, 1, 3 * PX, 12 * PX, N);
    upsample_kernel<<<gs((long)N * 3 * PX, BS), BS>>>(pool + O_S2, pool + O_MULTI + 3 * PX,
        3, 256, 256, 2, 3 * (PX / 4), 12 * PX, N);
    upsample_kernel<<<gs((long)N * 3 * PX, BS), BS>>>(pool + O_S3, pool + O_MULTI + 6 * PX,
        3, 128, 128, 4, 3 * (PX / 16), 12 * PX, N);
    upsample_kernel<<<gs((long)N * 3 * PX, BS), BS>>>(pool + O_S4, pool + O_MULTI + 9 * PX,
        3, 64, 64, 8, 3 * (PX / 64), 12 * PX, N);

    // ms = conv3(multi, 12->16), no act
    conv2d_kernel<3, 0><<<gs((long)N * 16 * 512 * 128, BS), BS>>>(
        pool + O_MULTI, 12, nullptr, 0, pool + O_MS, 16, w_mc, b_mc, 512, 512, N);

    // c2 = relu(conv5(x, 3->16))
    conv2d_kernel<5, 1><<<gs((long)N * 16 * 512 * 128, BS), BS>>>(
        x, 3, nullptr, 0, pool + O_C2, 16, w2, b2, 512, 512, N);

    // encoder
    maxpool_kernel<<<gs((long)N * 16 * 256 * 256, BS), BS>>>(pool + O_C2, pool + O_C2P, 16, 256, 256, N);
    conv2d_kernel<3, 1><<<gs((long)N * 32 * 256 * 64, BS), BS>>>(
        pool + O_C2P, 16, nullptr, 0, pool + O_C3, 32, w3, b3, 256, 256, N);
    maxpool_kernel<<<gs((long)N * 32 * 128 * 128, BS), BS>>>(pool + O_C3, pool + O_C3P, 32, 128, 128, N);
    conv2d_kernel<3, 1><<<gs((long)N * 32 * 128 * 32, BS), BS>>>(
        pool + O_C3P, 32, nullptr, 0, pool + O_C4, 32, w4, b4, 128, 128, N);
    maxpool_kernel<<<gs((long)N * 32 * 64 * 64, BS), BS>>>(pool + O_C4, pool + O_C4P, 32, 64, 64, N);
    conv2d_kernel<3, 1><<<gs((long)N * 32 * 64 * 16, BS), BS>>>(
        pool + O_C4P, 32, nullptr, 0, pool + O_C5, 32, w5, b5, 64, 64, N);
    maxpool_kernel<<<gs((long)N * 32 * 32 * 32, BS), BS>>>(pool + O_C5, pool + O_C5P, 32, 32, 32, N);
    conv2d_kernel<3, 1><<<gs((long)N * 64 * 32 * 8, BS), BS>>>(
        pool + O_C5P, 32, nullptr, 0, pool + O_C6, 64, w6, b6, 32, 32, N);

    // c6re = up2(relu(conv3(up2(c6), 64->64)))
    upsample_kernel<<<gs((long)N * 64 * 64 * 64, BS), BS>>>(pool + O_C6, pool + O_C6U,
        64, 32, 32, 2, 64L * 32 * 32, 64L * 64 * 64, N);
    conv2d_kernel<3, 1><<<gs((long)N * 64 * 64 * 16, BS), BS>>>(
        pool + O_C6U, 64, nullptr, 0, pool + O_C6S, 64, w6s, b6s, 64, 64, N);
    upsample_kernel<<<gs((long)N * 64 * 128 * 128, BS), BS>>>(pool + O_C6S, pool + O_C6RE,
        64, 64, 64, 2, 64L * 64 * 64, 64L * 128 * 128, N);

    // c7 = up2(relu(conv3(cat[c6re, c4], 96->32)))
    conv2d_kernel<3, 1><<<gs((long)N * 32 * 128 * 32, BS), BS>>>(
        pool + O_C6RE, 64, pool + O_C4, 32, pool + O_C7C, 32, w7, b7, 128, 128, N);
    upsample_kernel<<<gs((long)N * 32 * 256 * 256, BS), BS>>>(pool + O_C7C, pool + O_C7,
        32, 128, 128, 2, 32L * 128 * 128, 32L * 256 * 256, N);

    // c8 = up2(relu(conv3(cat[c7, c3], 64->16)))
    conv2d_kernel<3, 1><<<gs((long)N * 16 * 256 * 64, BS), BS>>>(
        pool + O_C7, 32, pool + O_C3, 32, pool + O_C8C, 16, w8, b8, 256, 256, N);
    upsample_kernel<<<gs((long)N * 16 * 512 * 512, BS), BS>>>(pool + O_C8C, pool + O_C8,
        16, 256, 256, 2, 16L * 256 * 256, 16L * 512 * 512, N);

    // c9 = tanh(conv3(cat[c8, c2], 32->64))
    conv2d_kernel<3, 2><<<gs((long)N * 64 * 512 * 128, BS), BS>>>(
        pool + O_C8, 16, pool + O_C2, 16, pool + O_C9, 64, w9, b9, 512, 512, N);

    // linear recurrent scans
    hscan12_kernel<<<gs(2L * 16 * 512, BS), BS>>>();
    vscan34_kernel<<<gs(2L * 16 * 512, BS), BS>>>();
    hscan56_kernel<<<gs(2L * 16 * 512, BS), BS>>>();
    vscan78_kernel<<<gs(2L * 16 * 512, BS), BS>>>();

    // c10 = relu(conv3(elt_max, 16->64))
    conv2d_kernel<3, 1><<<gs((long)N * 64 * 512 * 128, BS), BS>>>(
        pool + O_ELT, 16, nullptr, 0, pool + O_C10, 64, w10, b10, 512, 512, N);

    // out = relu(conv3(c10, 64->3))
    conv2d_kernel<3, 1><<<gs((long)N * 3 * 512 * 128, BS), BS>>>(
        pool + O_C10, 64, nullptr, 0, out, 3, w11, b11, 512, 512, N);
}

// round 2
// speedup vs baseline: 2.4582x; 2.4582x over previous
#include <cuda_runtime.h>
#include <math.h>

// ---------------------------------------------------------------------------
// Scratch pool
// ---------------------------------------------------------------------------
static constexpr long PX = 512L * 512;

static constexpr long O_S1    = 0;
static constexpr long O_S2    = O_S1    + 6 * PX;
static constexpr long O_S3    = O_S2    + 6 * (PX / 4);
static constexpr long O_S4    = O_S3    + 6 * (PX / 16);
static constexpr long O_MULTI = O_S4    + 6 * (PX / 64);
static constexpr long O_MS    = O_MULTI + 24 * PX;
static constexpr long O_C2    = O_MS    + 32 * PX;
static constexpr long O_C2P   = O_C2    + 32 * PX;
static constexpr long O_C3    = O_C2P   + 32 * (PX / 4);
static constexpr long O_C3P   = O_C3    + 64 * (PX / 4);
static constexpr long O_C4    = O_C3P   + 64 * (PX / 16);
static constexpr long O_C4P   = O_C4    + 64 * (PX / 16);
static constexpr long O_C5    = O_C4P   + 64 * (PX / 64);
static constexpr long O_C5P   = O_C5    + 64 * (PX / 64);
static constexpr long O_C6    = O_C5P   + 64 * (PX / 256);
static constexpr long O_C6U   = O_C6    + 128 * (PX / 256);
static constexpr long O_C6S   = O_C6U   + 128 * (PX / 64);
static constexpr long O_C6RE  = O_C6S   + 128 * (PX / 64);
static constexpr long O_C7C   = O_C6RE  + 128 * (PX / 16);
static constexpr long O_C7    = O_C7C   + 64 * (PX / 16);
static constexpr long O_C8C   = O_C7    + 64 * (PX / 4);
static constexpr long O_C8    = O_C8C   + 32 * (PX / 4);
static constexpr long O_C9    = O_C8    + 32 * PX;
static constexpr long O_H1    = O_C9    + 128 * PX;
static constexpr long O_H2    = O_H1    + 32 * PX;
static constexpr long O_H3    = O_H2    + 32 * PX;
static constexpr long O_H4    = O_H3    + 32 * PX;
static constexpr long O_HM    = O_H4    + 32 * PX;
static constexpr long O_ELT   = O_HM    + 32 * PX;
static constexpr long O_C10   = O_ELT   + 32 * PX;
static constexpr long POOL_TOTAL = O_C10 + 128 * PX;

__device__ float g_pool[POOL_TOTAL];

// ---------------------------------------------------------------------------
// Direct conv, SAME, stride 1, NCHW/OIHW. Register tiling: 4 x-outputs AND
// 4 cout-outputs per thread (16 accumulators). Weights staged in smem and
// read as broadcast float4 LDS. Two concatenated input sources supported.
// ACT: 0 none, 1 relu, 2 tanh
// ---------------------------------------------------------------------------
template <int K, int ACT>
__global__ void conv2d_co4(const float* __restrict__ srcA, int ca,
                           const float* __restrict__ srcB, int cb,
                           float* __restrict__ dst, int cout,
                           const float* __restrict__ w,
                           const float* __restrict__ bias,
                           int H, int W, int N, int nblk)
{
    extern __shared__ float w_s[];   // [ctot*K*K][4]  (co-minor)
    const int ctot = ca + cb;
    const int coG = (cout + 3) >> 2;

    int blk  = blockIdx.x;
    int pblk = blk % nblk;
    int cog  = (blk / nblk) % coG;
    int n    = blk / (nblk * coG);
    int co0  = cog << 2;

    // cooperative weight staging: w_s[e*4 + j] = w[(co0+j)*ctot*K*K + e]
    const int nw = ctot * K * K;
    for (int i = threadIdx.x; i < nw * 4; i += blockDim.x) {
        int j = i & 3;
        int e = i >> 2;
        int co = co0 + j;
        w_s[i] = (co < cout) ? __ldg(w + (long)co * nw + e) : 0.0f;
    }
    __syncthreads();

    const int W4 = W >> 2;
    int pos = pblk * blockDim.x + threadIdx.x;
    if (pos >= H * W4) return;
    int y  = pos / W4;
    int x0 = (pos % W4) << 2;
    constexpr int P = K / 2;

    float acc[4][4];
#pragma unroll
    for (int j = 0; j < 4; ++j) {
        float bv = (co0 + j < cout) ? __ldg(bias + co0 + j) : 0.0f;
#pragma unroll
        for (int m = 0; m < 4; ++m) acc[j][m] = bv;
    }

    bool xok[K + 3];
#pragma unroll
    for (int i = 0; i < K + 3; ++i) {
        int xx = x0 - P + i;
        xok[i] = (xx >= 0 && xx < W);
    }

    for (int ci = 0; ci < ctot; ++ci) {
        const float* plane = (ci < ca)
            ? srcA + ((long)n * ca + ci) * H * W
            : srcB + ((long)n * cb + (ci - ca)) * H * W;
        const float* ws = w_s + ci * (K * K * 4);

#pragma unroll
        for (int ky = 0; ky < K; ++ky) {
            int yy = y + ky - P;
            if (yy < 0 || yy >= H) continue;
            const float* r = plane + (long)yy * W + (x0 - P);
            float v[K + 3];
#pragma unroll
            for (int i = 0; i < K + 3; ++i)
                v[i] = xok[i] ? __ldg(r + i) : 0.0f;
#pragma unroll
            for (int kx = 0; kx < K; ++kx) {
                float4 wv = *reinterpret_cast<const float4*>(ws + (ky * K + kx) * 4);
#pragma unroll
                for (int m = 0; m < 4; ++m) {
                    acc[0][m] = fmaf(wv.x, v[kx + m], acc[0][m]);
                    acc[1][m] = fmaf(wv.y, v[kx + m], acc[1][m]);
                    acc[2][m] = fmaf(wv.z, v[kx + m], acc[2][m]);
                    acc[3][m] = fmaf(wv.w, v[kx + m], acc[3][m]);
                }
            }
        }
    }

#pragma unroll
    for (int j = 0; j < 4; ++j) {
        int co = co0 + j;
        if (co >= cout) break;
        float a0 = acc[j][0], a1 = acc[j][1], a2 = acc[j][2], a3 = acc[j][3];
        if (ACT == 1) {
            a0 = fmaxf(a0, 0.f); a1 = fmaxf(a1, 0.f);
            a2 = fmaxf(a2, 0.f); a3 = fmaxf(a3, 0.f);
        } else if (ACT == 2) {
            a0 = tanhf(a0); a1 = tanhf(a1); a2 = tanhf(a2); a3 = tanhf(a3);
        }
        long o = (((long)n * cout + co) * H + y) * W + x0;
        *reinterpret_cast<float4*>(dst + o) = make_float4(a0, a1, a2, a3);
    }
}

// ---------------------------------------------------------------------------
// 2x2 max pool, stride 2
// ---------------------------------------------------------------------------
__global__ void maxpool_kernel(const float* __restrict__ src, float* __restrict__ dst,
                               int C, int Ho, int Wo, int N)
{
    long idx = (long)blockIdx.x * blockDim.x + threadIdx.x;
    long total = (long)N * C * Ho * Wo;
    if (idx >= total) return;
    int x = (int)(idx % Wo);  long t = idx / Wo;
    int y = (int)(t % Ho);    t /= Ho;
    int c = (int)(t % C);
    int n = (int)(t / C);
    int Hi = Ho * 2, Wi = Wo * 2;
    const float* p = src + (((long)n * C + c) * Hi + 2 * y) * Wi + 2 * x;
    dst[idx] = fmaxf(fmaxf(p[0], p[1]), fmaxf(p[Wi], p[Wi + 1]));
}

// ---------------------------------------------------------------------------
// Bilinear upsample (half-pixel, clamped == jax.image.resize 'bilinear')
// ---------------------------------------------------------------------------
__global__ void upsample_kernel(const float* __restrict__ src, float* __restrict__ dst,
                                int C, int Hs, int Ws, int scale,
                                long sBS, long dBS, int N)
{
    int Hd = Hs * scale, Wd = Ws * scale;
    long idx = (long)blockIdx.x * blockDim.x + threadIdx.x;
    long total = (long)N * C * Hd * Wd;
    if (idx >= total) return;
    int x = (int)(idx % Wd);  long t = idx / Wd;
    int y = (int)(t % Hd);    t /= Hd;
    int c = (int)(t % C);
    int n = (int)(t / C);

    float inv = 1.0f / (float)scale;
    float fy = (y + 0.5f) * inv - 0.5f;
    float fx = (x + 0.5f) * inv - 0.5f;
    int y0 = (int)floorf(fy);
    int x0 = (int)floorf(fx);
    float wy = fy - (float)y0;
    float wx = fx - (float)x0;
    int y0c = min(max(y0, 0), Hs - 1);
    int y1c = min(max(y0 + 1, 0), Hs - 1);
    int x0c = min(max(x0, 0), Ws - 1);
    int x1c = min(max(x0 + 1, 0), Ws - 1);

    const float* p = src + n * sBS + (long)c * Hs * Ws;
    float v00 = p[(long)y0c * Ws + x0c];
    float v01 = p[(long)y0c * Ws + x1c];
    float v10 = p[(long)y1c * Ws + x0c];
    float v11 = p[(long)y1c * Ws + x1c];
    float v = (1.f - wy) * ((1.f - wx) * v00 + wx * v01)
            +        wy  * ((1.f - wx) * v10 + wx * v11);

    dst[n * dBS + ((long)c * Hd + y) * Wd + x] = v;
}

// ---------------------------------------------------------------------------
// Horizontal scans: one warp per row. Chunk-serial (16 elems/lane) affine
// aggregate (A,B), warp shfl scan, then replay with prefix. Fully coalesced.
// comb(prev,cur): A = Ap*A ; B = A*Bp + B   (applied before A update)
// ---------------------------------------------------------------------------
__device__ __forceinline__ float warp_affine_prefix(float& A, float& B, int lane)
{
    // inclusive scan of (A,B) pairs along lanes
#pragma unroll
    for (int d = 1; d < 32; d <<= 1) {
        float Ap = __shfl_up_sync(0xffffffffu, A, d);
        float Bp = __shfl_up_sync(0xffffffffu, B, d);
        if (lane >= d) { B = fmaf(A, Bp, B); A *= Ap; }
    }
    float yin = __shfl_up_sync(0xffffffffu, B, 1);
    return (lane == 0) ? 0.0f : yin;   // exclusive prefix state
}

__global__ void hscan12_warp()   // h1 = scan(gx1, ms); h2 = scan(gx1, ms rev-x)
{
    int gw = (blockIdx.x * blockDim.x + threadIdx.x) >> 5;
    int lane = threadIdx.x & 31;
    if (gw >= 2 * 16 * 512) return;
    int y = gw % 512;  int t = gw / 512;
    int c = t % 16;    int n = t / 16;
    long rp = (((long)n * 16 + c) * 512 + y) * 512;
    const float* a = g_pool + O_C9 + (((long)n * 64 + c) * 512 + y) * 512;
    const float* u = g_pool + O_MS + rp;
    float* h1 = g_pool + O_H1 + rp;
    float* h2 = g_pool + O_H2 + rp;
    int x0 = lane * 16;

    // --- h1 (u forward) ---
    float A = 1.f, B = 0.f;
#pragma unroll
    for (int i = 0; i < 16; ++i) {
        float av = a[x0 + i];
        B = fmaf(av, B, (1.f - av) * u[x0 + i]);
        A *= av;
    }
    float yv = warp_affine_prefix(A, B, lane);
#pragma unroll
    for (int i = 0; i < 16; ++i) {
        float av = a[x0 + i];
        yv = fmaf(av, yv, (1.f - av) * u[x0 + i]);
        h1[x0 + i] = yv;
    }

    // --- h2 (u reversed) ---
    A = 1.f; B = 0.f;
#pragma unroll
    for (int i = 0; i < 16; ++i) {
        float av = a[x0 + i];
        B = fmaf(av, B, (1.f - av) * u[511 - (x0 + i)]);
        A *= av;
    }
    yv = warp_affine_prefix(A, B, lane);
#pragma unroll
    for (int i = 0; i < 16; ++i) {
        float av = a[x0 + i];
        yv = fmaf(av, yv, (1.f - av) * u[511 - (x0 + i)]);
        h2[x0 + i] = yv;
    }
}

__global__ void hscan56_warp()   // hm = max(scan(gx2,h1), scan(gx2,h2 rev-x))
{
    int gw = (blockIdx.x * blockDim.x + threadIdx.x) >> 5;
    int lane = threadIdx.x & 31;
    if (gw >= 2 * 16 * 512) return;
    int y = gw % 512;  int t = gw / 512;
    int c = t % 16;    int n = t / 16;
    long rp = (((long)n * 16 + c) * 512 + y) * 512;
    const float* a  = g_pool + O_C9 + (((long)n * 64 + 32 + c) * 512 + y) * 512;
    const float* h1 = g_pool + O_H1 + rp;
    const float* h2 = g_pool + O_H2 + rp;
    float* hm = g_pool + O_HM + rp;
    int x0 = lane * 16;

    float A = 1.f, B = 0.f;
#pragma unroll
    for (int i = 0; i < 16; ++i) {
        float av = a[x0 + i];
        B = fmaf(av, B, (1.f - av) * h1[x0 + i]);
        A *= av;
    }
    float y5 = warp_affine_prefix(A, B, lane);

    A = 1.f; B = 0.f;
#pragma unroll
    for (int i = 0; i < 16; ++i) {
        float av = a[x0 + i];
        B = fmaf(av, B, (1.f - av) * h2[511 - (x0 + i)]);
        A *= av;
    }
    float y6 = warp_affine_prefix(A, B, lane);

#pragma unroll
    for (int i = 0; i < 16; ++i) {
        float av = a[x0 + i];
        y5 = fmaf(av, y5, (1.f - av) * h1[x0 + i]);
        y6 = fmaf(av, y6, (1.f - av) * h2[511 - (x0 + i)]);
        hm[x0 + i] = fmaxf(y5, y6);
    }
}

// ---------------------------------------------------------------------------
// Vertical scans (coalesced across x; serial over y)
// ---------------------------------------------------------------------------
__global__ void vscan34_kernel()
{
    int idx = blockIdx.x * blockDim.x + threadIdx.x;
    if (idx >= 2 * 16 * 512) return;
    int x = idx % 512;  int t = idx / 512;
    int c = t % 16;     int n = t / 16;
    long pp = ((long)n * 16 + c) * 512 * 512;
    const float* gx1 = g_pool + O_C9 + ((long)n * 64 + c) * 512 * 512;
    const float* gy1 = g_pool + O_C9 + ((long)n * 64 + 16 + c) * 512 * 512;
    const float* u   = g_pool + O_MS + pp;
    float* h3 = g_pool + O_H3 + pp;
    float* h4 = g_pool + O_H4 + pp;
    float y3 = 0.f, y4 = 0.f;
    for (int ty = 0; ty < 512; ++ty) {
        float av = (ty == 0) ? gy1[x] : gx1[(long)ty * 512 + x];
        float om = 1.f - av;
        y3 = fmaf(av, y3, om * u[(long)ty * 512 + x]);
        y4 = fmaf(av, y4, om * u[(long)(511 - ty) * 512 + x]);
        h3[(long)ty * 512 + x] = y3;
        h4[(long)ty * 512 + x] = y4;
    }
}

__global__ void vscan78_kernel()
{
    int idx = blockIdx.x * blockDim.x + threadIdx.x;
    if (idx >= 2 * 16 * 512) return;
    int x = idx % 512;  int t = idx / 512;
    int c = t % 16;     int n = t / 16;
    long pp = ((long)n * 16 + c) * 512 * 512;
    const float* a  = g_pool + O_C9 + ((long)n * 64 + 48 + c) * 512 * 512;
    const float* h3 = g_pool + O_H3 + pp;
    const float* h4 = g_pool + O_H4 + pp;
    const float* hm = g_pool + O_HM + pp;
    float* elt = g_pool + O_ELT + pp;
    float y7 = 0.f, y8 = 0.f;
    for (int ty = 0; ty < 512; ++ty) {
        float av = a[(long)ty * 512 + x];
        float om = 1.f - av;
        y7 = fmaf(av, y7, om * h3[(long)ty * 512 + x]);
        y8 = fmaf(av, y8, om * h4[(long)(511 - ty) * 512 + x]);
        elt[(long)ty * 512 + x] = fmaxf(hm[(long)ty * 512 + x], fmaxf(y7, y8));
    }
}

// ---------------------------------------------------------------------------
// Launch
// ---------------------------------------------------------------------------
static inline int gs(long total, int bs) { return (int)((total + bs - 1) / bs); }

template <int K, int ACT>
static void launch_conv(const float* srcA, int ca, const float* srcB, int cb,
                        float* dst, int cout, const float* w, const float* b,
                        int H, int W, int N)
{
    const int BT = 128;
    int W4 = W >> 2;
    int nblk = (H * W4 + BT - 1) / BT;
    int coG = (cout + 3) >> 2;
    int blocks = N * coG * nblk;
    int smem = (ca + cb) * K * K * 4 * (int)sizeof(float);
    conv2d_co4<K, ACT><<<blocks, BT, smem>>>(srcA, ca, srcB, cb, dst, cout, w, b, H, W, N, nblk);
}

extern "C" void kernel_launch(void* const* d_in, const int* in_sizes, int n_in,
                              void* d_out, int out_size)
{
    const float* x    = (const float*)d_in[0];
    const float* w_s1 = (const float*)d_in[1];  const float* b_s1 = (const float*)d_in[2];
    const float* w_mc = (const float*)d_in[3];  const float* b_mc = (const float*)d_in[4];
    const float* w2   = (const float*)d_in[5];  const float* b2   = (const float*)d_in[6];
    const float* w3   = (const float*)d_in[7];  const float* b3   = (const float*)d_in[8];
    const float* w4   = (const float*)d_in[9];  const float* b4   = (const float*)d_in[10];
    const float* w5   = (const float*)d_in[11]; const float* b5   = (const float*)d_in[12];
    const float* w6   = (const float*)d_in[13]; const float* b6   = (const float*)d_in[14];
    const float* w6s  = (const float*)d_in[15]; const float* b6s  = (const float*)d_in[16];
    const float* w7   = (const float*)d_in[17]; const float* b7   = (const float*)d_in[18];
    const float* w8   = (const float*)d_in[19]; const float* b8   = (const float*)d_in[20];
    const float* w9   = (const float*)d_in[21]; const float* b9   = (const float*)d_in[22];
    const float* w10  = (const float*)d_in[23]; const float* b10  = (const float*)d_in[24];
    const float* w11  = (const float*)d_in[25]; const float* b11  = (const float*)d_in[26];
    float* out = (float*)d_out;

    float* pool = nullptr;
    cudaGetSymbolAddress((void**)&pool, g_pool);

    const int BS = 256;
    const int N = 2;

    // s1 = conv3(x, 3->3)
    launch_conv<3, 0>(x, 3, nullptr, 0, pool + O_S1, 3, w_s1, b_s1, 512, 512, N);
    maxpool_kernel<<<gs((long)N * 3 * 256 * 256, BS), BS>>>(pool + O_S1, pool + O_S2, 3, 256, 256, N);
    maxpool_kernel<<<gs((long)N * 3 * 128 * 128, BS), BS>>>(pool + O_S2, pool + O_S3, 3, 128, 128, N);
    maxpool_kernel<<<gs((long)N * 3 * 64 * 64, BS), BS>>>(pool + O_S3, pool + O_S4, 3, 64, 64, N);

    // multi concat
    upsample_kernel<<<gs((long)N * 3 * PX, BS), BS>>>(pool + O_S1, pool + O_MULTI + 0 * PX,
        3, 512, 512, 1, 3 * PX, 12 * PX, N);
    upsample_kernel<<<gs((long)N * 3 * PX, BS), BS>>>(pool + O_S2, pool + O_MULTI + 3 * PX,
        3, 256, 256, 2, 3 * (PX / 4), 12 * PX, N);
    upsample_kernel<<<gs((long)N * 3 * PX, BS), BS>>>(pool + O_S3, pool + O_MULTI + 6 * PX,
        3, 128, 128, 4, 3 * (PX / 16), 12 * PX, N);
    upsample_kernel<<<gs((long)N * 3 * PX, BS), BS>>>(pool + O_S4, pool + O_MULTI + 9 * PX,
        3, 64, 64, 8, 3 * (PX / 64), 12 * PX, N);

    // ms = conv3(multi, 12->16)
    launch_conv<3, 0>(pool + O_MULTI, 12, nullptr, 0, pool + O_MS, 16, w_mc, b_mc, 512, 512, N);

    // c2 = relu(conv5(x, 3->16))
    launch_conv<5, 1>(x, 3, nullptr, 0, pool + O_C2, 16, w2, b2, 512, 512, N);

    // encoder
    maxpool_kernel<<<gs((long)N * 16 * 256 * 256, BS), BS>>>(pool + O_C2, pool + O_C2P, 16, 256, 256, N);
    launch_conv<3, 1>(pool + O_C2P, 16, nullptr, 0, pool + O_C3, 32, w3, b3, 256, 256, N);
    maxpool_kernel<<<gs((long)N * 32 * 128 * 128, BS), BS>>>(pool + O_C3, pool + O_C3P, 32, 128, 128, N);
    launch_conv<3, 1>(pool + O_C3P, 32, nullptr, 0, pool + O_C4, 32, w4, b4, 128, 128, N);
    maxpool_kernel<<<gs((long)N * 32 * 64 * 64, BS), BS>>>(pool + O_C4, pool + O_C4P, 32, 64, 64, N);
    launch_conv<3, 1>(pool + O_C4P, 32, nullptr, 0, pool + O_C5, 32, w5, b5, 64, 64, N);
    maxpool_kernel<<<gs((long)N * 32 * 32 * 32, BS), BS>>>(pool + O_C5, pool + O_C5P, 32, 32, 32, N);
    launch_conv<3, 1>(pool + O_C5P, 32, nullptr, 0, pool + O_C6, 64, w6, b6, 32, 32, N);

    // c6re
    upsample_kernel<<<gs((long)N * 64 * 64 * 64, BS), BS>>>(pool + O_C6, pool + O_C6U,
        64, 32, 32, 2, 64L * 32 * 32, 64L * 64 * 64, N);
    launch_conv<3, 1>(pool + O_C6U, 64, nullptr, 0, pool + O_C6S, 64, w6s, b6s, 64, 64, N);
    upsample_kernel<<<gs((long)N * 64 * 128 * 128, BS), BS>>>(pool + O_C6S, pool + O_C6RE,
        64, 64, 64, 2, 64L * 64 * 64, 64L * 128 * 128, N);

    // c7
    launch_conv<3, 1>(pool + O_C6RE, 64, pool + O_C4, 32, pool + O_C7C, 32, w7, b7, 128, 128, N);
    upsample_kernel<<<gs((long)N * 32 * 256 * 256, BS), BS>>>(pool + O_C7C, pool + O_C7,
        32, 128, 128, 2, 32L * 128 * 128, 32L * 256 * 256, N);

    // c8
    launch_conv<3, 1>(pool + O_C7, 32, pool + O_C3, 32, pool + O_C8C, 16, w8, b8, 256, 256, N);
    upsample_kernel<<<gs((long)N * 16 * 512 * 512, BS), BS>>>(pool + O_C8C, pool + O_C8,
        16, 256, 256, 2, 16L * 256 * 256, 16L * 512 * 512, N);

    // c9 = tanh(conv3(cat[c8, c2], 32->64))
    launch_conv<3, 2>(pool + O_C8, 16, pool + O_C2, 16, pool + O_C9, 64, w9, b9, 512, 512, N);

    // scans
    hscan12_warp<<<gs(2L * 16 * 512 * 32, BS), BS>>>();
    vscan34_kernel<<<gs(2L * 16 * 512, BS), BS>>>();
    hscan56_warp<<<gs(2L * 16 * 512 * 32, BS), BS>>>();
    vscan78_kernel<<<gs(2L * 16 * 512, BS), BS>>>();

    // c10 = relu(conv3(elt_max, 16->64))
    launch_conv<3, 1>(pool + O_ELT, 16, nullptr, 0, pool + O_C10, 64, w10, b10, 512, 512, N);

    // out = relu(conv3(c10, 64->3))
    launch_conv<3, 1>(pool + O_C10, 64, nullptr, 0, out, 3, w11, b11, 512, 512, N);
}

// round 3
// speedup vs baseline: 2.7777x; 1.1300x over previous
#include <cuda_runtime.h>
#include <math.h>

// ---------------------------------------------------------------------------
// Scratch pool
// ---------------------------------------------------------------------------
static constexpr long PX = 512L * 512;

static constexpr long O_S1    = 0;
static constexpr long O_S2    = O_S1    + 6 * PX;
static constexpr long O_S3    = O_S2    + 6 * (PX / 4);
static constexpr long O_S4    = O_S3    + 6 * (PX / 16);
static constexpr long O_MULTI = O_S4    + 6 * (PX / 64);
static constexpr long O_MS    = O_MULTI + 24 * PX;
static constexpr long O_C2    = O_MS    + 32 * PX;
static constexpr long O_C2P   = O_C2    + 32 * PX;
static constexpr long O_C3    = O_C2P   + 32 * (PX / 4);
static constexpr long O_C3P   = O_C3    + 64 * (PX / 4);
static constexpr long O_C4    = O_C3P   + 64 * (PX / 16);
static constexpr long O_C4P   = O_C4    + 64 * (PX / 16);
static constexpr long O_C5    = O_C4P   + 64 * (PX / 64);
static constexpr long O_C5P   = O_C5    + 64 * (PX / 64);
static constexpr long O_C6    = O_C5P   + 64 * (PX / 256);
static constexpr long O_C6U   = O_C6    + 128 * (PX / 256);
static constexpr long O_C6S   = O_C6U   + 128 * (PX / 64);
static constexpr long O_C6RE  = O_C6S   + 128 * (PX / 64);
static constexpr long O_C7C   = O_C6RE  + 128 * (PX / 16);
static constexpr long O_C7    = O_C7C   + 64 * (PX / 16);
static constexpr long O_C8C   = O_C7    + 64 * (PX / 4);
static constexpr long O_C8    = O_C8C   + 32 * (PX / 4);
static constexpr long O_C9    = O_C8    + 32 * PX;
static constexpr long O_H1    = O_C9    + 128 * PX;
static constexpr long O_H2    = O_H1    + 32 * PX;
static constexpr long O_H3    = O_H2    + 32 * PX;
static constexpr long O_H4    = O_H3    + 32 * PX;
static constexpr long O_HM    = O_H4    + 32 * PX;
static constexpr long O_ELT   = O_HM    + 32 * PX;
static constexpr long O_C10   = O_ELT   + 32 * PX;
static constexpr long POOL_TOTAL = O_C10 + 128 * PX;

__device__ float g_pool[POOL_TOTAL];

// ---------------------------------------------------------------------------
// packed f32x2 helpers (sm_103a FFMA2 path — ptxas never auto-fuses)
// ---------------------------------------------------------------------------
typedef unsigned long long ull;

__device__ __forceinline__ ull pk2(float lo, float hi) {
    ull r;
    asm("mov.b64 %0, {%1, %2};" : "=l"(r) : "f"(lo), "f"(hi));
    return r;
}
__device__ __forceinline__ void upk2(float& lo, float& hi, ull v) {
    asm("mov.b64 {%0, %1}, %2;" : "=f"(lo), "=f"(hi) : "l"(v));
}
__device__ __forceinline__ ull fma2(ull a, ull b, ull c) {
    ull d;
    asm("fma.rn.f32x2 %0, %1, %2, %3;" : "=l"(d) : "l"(a), "l"(b), "l"(c));
    return d;
}

// ---------------------------------------------------------------------------
// Direct conv, SAME, stride 1, NCHW/OIHW.
// Tiling: 4 x-outputs per thread, CO couts per thread packed as CO/2 f32x2
// accumulator pairs. Weights staged in smem as [elem][co] so an LDS.64 yields
// {w_co, w_co+1} directly. Input values packed once per tap as {v,v}.
// ACT: 0 none, 1 relu, 2 tanh. Two concatenated sources (srcB optional).
// ---------------------------------------------------------------------------
template <int K, int ACT, int CO>
__global__ __launch_bounds__(128)
void conv2d_pk(const float* __restrict__ srcA, int ca,
               const float* __restrict__ srcB, int cb,
               float* __restrict__ dst, int cout,
               const float* __restrict__ w,
               const float* __restrict__ bias,
               int H, int W, int N, int nblk)
{
    extern __shared__ float w_s[];   // [ctot*K*K][CO]
    const int ctot = ca + cb;
    const int coG = (cout + CO - 1) / CO;

    int blk  = blockIdx.x;
    int pblk = blk % nblk;
    int cog  = (blk / nblk) % coG;
    int n    = blk / (nblk * coG);
    int co0  = cog * CO;

    // stage weights: w_s[e*CO + j] = w[(co0+j)*nw + e]
    const int nw = ctot * K * K;
    for (int i = threadIdx.x; i < nw * CO; i += blockDim.x) {
        int e = i / CO;
        int j = i - e * CO;
        int co = co0 + j;
        w_s[i] = (co < cout) ? __ldg(w + (long)co * nw + e) : 0.0f;
    }
    __syncthreads();

    const int W4 = W >> 2;
    int pos = pblk * blockDim.x + threadIdx.x;
    if (pos >= H * W4) return;
    int y  = pos / W4;
    int x0 = (pos % W4) << 2;
    constexpr int P  = K / 2;
    constexpr int CP = CO / 2;    // cout pairs

    ull acc[CP][4];
#pragma unroll
    for (int cp = 0; cp < CP; ++cp) {
        float b0 = (co0 + 2 * cp     < cout) ? __ldg(bias + co0 + 2 * cp)     : 0.0f;
        float b1 = (co0 + 2 * cp + 1 < cout) ? __ldg(bias + co0 + 2 * cp + 1) : 0.0f;
        ull bp = pk2(b0, b1);
#pragma unroll
        for (int m = 0; m < 4; ++m) acc[cp][m] = bp;
    }

    bool xok[K + 3];
#pragma unroll
    for (int i = 0; i < K + 3; ++i) {
        int xx = x0 - P + i;
        xok[i] = (xx >= 0 && xx < W);
    }

    for (int ci = 0; ci < ctot; ++ci) {
        const float* plane = (ci < ca)
            ? srcA + ((long)n * ca + ci) * H * W
            : srcB + ((long)n * cb + (ci - ca)) * H * W;
        const float* ws = w_s + ci * (K * K * CO);

#pragma unroll
        for (int ky = 0; ky < K; ++ky) {
            int yy = y + ky - P;
            if (yy < 0 || yy >= H) continue;
            const float* r = plane + (long)yy * W + (x0 - P);
            ull pv[K + 3];
#pragma unroll
            for (int i = 0; i < K + 3; ++i) {
                float v = xok[i] ? __ldg(r + i) : 0.0f;
                pv[i] = pk2(v, v);
            }
#pragma unroll
            for (int kx = 0; kx < K; ++kx) {
                const float* we = ws + (ky * K + kx) * CO;
#pragma unroll
                for (int cp = 0; cp < CP; ++cp) {
                    ull wv = *reinterpret_cast<const ull*>(we + 2 * cp);
#pragma unroll
                    for (int m = 0; m < 4; ++m)
                        acc[cp][m] = fma2(wv, pv[kx + m], acc[cp][m]);
                }
            }
        }
    }

#pragma unroll
    for (int cp = 0; cp < CP; ++cp) {
        float o0[4], o1[4];
#pragma unroll
        for (int m = 0; m < 4; ++m) upk2(o0[m], o1[m], acc[cp][m]);
#pragma unroll
        for (int h = 0; h < 2; ++h) {
            int co = co0 + 2 * cp + h;
            if (co >= cout) break;
            float* ov = h ? o1 : o0;
            float a0 = ov[0], a1 = ov[1], a2 = ov[2], a3 = ov[3];
            if (ACT == 1) {
                a0 = fmaxf(a0, 0.f); a1 = fmaxf(a1, 0.f);
                a2 = fmaxf(a2, 0.f); a3 = fmaxf(a3, 0.f);
            } else if (ACT == 2) {
                a0 = tanhf(a0); a1 = tanhf(a1); a2 = tanhf(a2); a3 = tanhf(a3);
            }
            long o = (((long)n * cout + co) * H + y) * W + x0;
            *reinterpret_cast<float4*>(dst + o) = make_float4(a0, a1, a2, a3);
        }
    }
}

// ---------------------------------------------------------------------------
// 2x2 max pool, stride 2
// ---------------------------------------------------------------------------
__global__ void maxpool_kernel(const float* __restrict__ src, float* __restrict__ dst,
                               int C, int Ho, int Wo, int N)
{
    long idx = (long)blockIdx.x * blockDim.x + threadIdx.x;
    long total = (long)N * C * Ho * Wo;
    if (idx >= total) return;
    int x = (int)(idx % Wo);  long t = idx / Wo;
    int y = (int)(t % Ho);    t /= Ho;
    int c = (int)(t % C);
    int n = (int)(t / C);
    int Hi = Ho * 2, Wi = Wo * 2;
    const float* p = src + (((long)n * C + c) * Hi + 2 * y) * Wi + 2 * x;
    dst[idx] = fmaxf(fmaxf(p[0], p[1]), fmaxf(p[Wi], p[Wi + 1]));
}

// ---------------------------------------------------------------------------
// Bilinear upsample (half-pixel, clamped == jax.image.resize 'bilinear')
// ---------------------------------------------------------------------------
__global__ void upsample_kernel(const float* __restrict__ src, float* __restrict__ dst,
                                int C, int Hs, int Ws, int scale,
                                long sBS, long dBS, int N)
{
    int Hd = Hs * scale, Wd = Ws * scale;
    long idx = (long)blockIdx.x * blockDim.x + threadIdx.x;
    long total = (long)N * C * Hd * Wd;
    if (idx >= total) return;
    int x = (int)(idx % Wd);  long t = idx / Wd;
    int y = (int)(t % Hd);    t /= Hd;
    int c = (int)(t % C);
    int n = (int)(t / C);

    float inv = 1.0f / (float)scale;
    float fy = (y + 0.5f) * inv - 0.5f;
    float fx = (x + 0.5f) * inv - 0.5f;
    int y0 = (int)floorf(fy);
    int x0 = (int)floorf(fx);
    float wy = fy - (float)y0;
    float wx = fx - (float)x0;
    int y0c = min(max(y0, 0), Hs - 1);
    int y1c = min(max(y0 + 1, 0), Hs - 1);
    int x0c = min(max(x0, 0), Ws - 1);
    int x1c = min(max(x0 + 1, 0), Ws - 1);

    const float* p = src + n * sBS + (long)c * Hs * Ws;
    float v00 = p[(long)y0c * Ws + x0c];
    float v01 = p[(long)y0c * Ws + x1c];
    float v10 = p[(long)y1c * Ws + x0c];
    float v11 = p[(long)y1c * Ws + x1c];
    float v = (1.f - wy) * ((1.f - wx) * v00 + wx * v01)
            +        wy  * ((1.f - wx) * v10 + wx * v11);

    dst[n * dBS + ((long)c * Hd + y) * Wd + x] = v;
}

// ---------------------------------------------------------------------------
// Horizontal scans: one warp per row (chunk-serial + shfl affine scan)
// ---------------------------------------------------------------------------
__device__ __forceinline__ float warp_affine_prefix(float& A, float& B, int lane)
{
#pragma unroll
    for (int d = 1; d < 32; d <<= 1) {
        float Ap = __shfl_up_sync(0xffffffffu, A, d);
        float Bp = __shfl_up_sync(0xffffffffu, B, d);
        if (lane >= d) { B = fmaf(A, Bp, B); A *= Ap; }
    }
    float yin = __shfl_up_sync(0xffffffffu, B, 1);
    return (lane == 0) ? 0.0f : yin;
}

__global__ void hscan12_warp()
{
    int gw = (blockIdx.x * blockDim.x + threadIdx.x) >> 5;
    int lane = threadIdx.x & 31;
    if (gw >= 2 * 16 * 512) return;
    int y = gw % 512;  int t = gw / 512;
    int c = t % 16;    int n = t / 16;
    long rp = (((long)n * 16 + c) * 512 + y) * 512;
    const float* a = g_pool + O_C9 + (((long)n * 64 + c) * 512 + y) * 512;
    const float* u = g_pool + O_MS + rp;
    float* h1 = g_pool + O_H1 + rp;
    float* h2 = g_pool + O_H2 + rp;
    int x0 = lane * 16;

    float A = 1.f, B = 0.f;
#pragma unroll
    for (int i = 0; i < 16; ++i) {
        float av = a[x0 + i];
        B = fmaf(av, B, (1.f - av) * u[x0 + i]);
        A *= av;
    }
    float yv = warp_affine_prefix(A, B, lane);
#pragma unroll
    for (int i = 0; i < 16; ++i) {
        float av = a[x0 + i];
        yv = fmaf(av, yv, (1.f - av) * u[x0 + i]);
        h1[x0 + i] = yv;
    }

    A = 1.f; B = 0.f;
#pragma unroll
    for (int i = 0; i < 16; ++i) {
        float av = a[x0 + i];
        B = fmaf(av, B, (1.f - av) * u[511 - (x0 + i)]);
        A *= av;
    }
    yv = warp_affine_prefix(A, B, lane);
#pragma unroll
    for (int i = 0; i < 16; ++i) {
        float av = a[x0 + i];
        yv = fmaf(av, yv, (1.f - av) * u[511 - (x0 + i)]);
        h2[x0 + i] = yv;
    }
}

__global__ void hscan56_warp()
{
    int gw = (blockIdx.x * blockDim.x + threadIdx.x) >> 5;
    int lane = threadIdx.x & 31;
    if (gw >= 2 * 16 * 512) return;
    int y = gw % 512;  int t = gw / 512;
    int c = t % 16;    int n = t / 16;
    long rp = (((long)n * 16 + c) * 512 + y) * 512;
    const float* a  = g_pool + O_C9 + (((long)n * 64 + 32 + c) * 512 + y) * 512;
    const float* h1 = g_pool + O_H1 + rp;
    const float* h2 = g_pool + O_H2 + rp;
    float* hm = g_pool + O_HM + rp;
    int x0 = lane * 16;

    float A = 1.f, B = 0.f;
#pragma unroll
    for (int i = 0; i < 16; ++i) {
        float av = a[x0 + i];
        B = fmaf(av, B, (1.f - av) * h1[x0 + i]);
        A *= av;
    }
    float y5 = warp_affine_prefix(A, B, lane);

    A = 1.f; B = 0.f;
#pragma unroll
    for (int i = 0; i < 16; ++i) {
        float av = a[x0 + i];
        B = fmaf(av, B, (1.f - av) * h2[511 - (x0 + i)]);
        A *= av;
    }
    float y6 = warp_affine_prefix(A, B, lane);

#pragma unroll
    for (int i = 0; i < 16; ++i) {
        float av = a[x0 + i];
        y5 = fmaf(av, y5, (1.f - av) * h1[x0 + i]);
        y6 = fmaf(av, y6, (1.f - av) * h2[511 - (x0 + i)]);
        hm[x0 + i] = fmaxf(y5, y6);
    }
}

// ---------------------------------------------------------------------------
// Vertical scans (coalesced across x; serial over y)
// ---------------------------------------------------------------------------
__global__ void vscan34_kernel()
{
    int idx = blockIdx.x * blockDim.x + threadIdx.x;
    if (idx >= 2 * 16 * 512) return;
    int x = idx % 512;  int t = idx / 512;
    int c = t % 16;     int n = t / 16;
    long pp = ((long)n * 16 + c) * 512 * 512;
    const float* gx1 = g_pool + O_C9 + ((long)n * 64 + c) * 512 * 512;
    const float* gy1 = g_pool + O_C9 + ((long)n * 64 + 16 + c) * 512 * 512;
    const float* u   = g_pool + O_MS + pp;
    float* h3 = g_pool + O_H3 + pp;
    float* h4 = g_pool + O_H4 + pp;
    float y3 = 0.f, y4 = 0.f;
    for (int ty = 0; ty < 512; ++ty) {
        float av = (ty == 0) ? gy1[x] : gx1[(long)ty * 512 + x];
        float om = 1.f - av;
        y3 = fmaf(av, y3, om * u[(long)ty * 512 + x]);
        y4 = fmaf(av, y4, om * u[(long)(511 - ty) * 512 + x]);
        h3[(long)ty * 512 + x] = y3;
        h4[(long)ty * 512 + x] = y4;
    }
}

__global__ void vscan78_kernel()
{
    int idx = blockIdx.x * blockDim.x + threadIdx.x;
    if (idx >= 2 * 16 * 512) return;
    int x = idx % 512;  int t = idx / 512;
    int c = t % 16;     int n = t / 16;
    long pp = ((long)n * 16 + c) * 512 * 512;
    const float* a  = g_pool + O_C9 + ((long)n * 64 + 48 + c) * 512 * 512;
    const float* h3 = g_pool + O_H3 + pp;
    const float* h4 = g_pool + O_H4 + pp;
    const float* hm = g_pool + O_HM + pp;
    float* elt = g_pool + O_ELT + pp;
    float y7 = 0.f, y8 = 0.f;
    for (int ty = 0; ty < 512; ++ty) {
        float av = a[(long)ty * 512 + x];
        float om = 1.f - av;
        y7 = fmaf(av, y7, om * h3[(long)ty * 512 + x]);
        y8 = fmaf(av, y8, om * h4[(long)(511 - ty) * 512 + x]);
        elt[(long)ty * 512 + x] = fmaxf(hm[(long)ty * 512 + x], fmaxf(y7, y8));
    }
}

// ---------------------------------------------------------------------------
// Launch helpers
// ---------------------------------------------------------------------------
static inline int gs(long total, int bs) { return (int)((total + bs - 1) / bs); }

template <int K, int ACT, int CO>
static void launch_conv(const float* srcA, int ca, const float* srcB, int cb,
                        float* dst, int cout, const float* w, const float* b,
                        int H, int W, int N)
{
    const int BT = 128;
    int W4 = W >> 2;
    int nblk = (H * W4 + BT - 1) / BT;
    int coG = (cout + CO - 1) / CO;
    int blocks = N * coG * nblk;
    int smem = (ca + cb) * K * K * CO * (int)sizeof(float);
    conv2d_pk<K, ACT, CO><<<blocks, BT, smem>>>(srcA, ca, srcB, cb, dst, cout, w, b, H, W, N, nblk);
}

extern "C" void kernel_launch(void* const* d_in, const int* in_sizes, int n_in,
                              void* d_out, int out_size)
{
    const float* x    = (const float*)d_in[0];
    const float* w_s1 = (const float*)d_in[1];  const float* b_s1 = (const float*)d_in[2];
    const float* w_mc = (const float*)d_in[3];  const float* b_mc = (const float*)d_in[4];
    const float* w2   = (const float*)d_in[5];  const float* b2   = (const float*)d_in[6];
    const float* w3   = (const float*)d_in[7];  const float* b3   = (const float*)d_in[8];
    const float* w4   = (const float*)d_in[9];  const float* b4   = (const float*)d_in[10];
    const float* w5   = (const float*)d_in[11]; const float* b5   = (const float*)d_in[12];
    const float* w6   = (const float*)d_in[13]; const float* b6   = (const float*)d_in[14];
    const float* w6s  = (const float*)d_in[15]; const float* b6s  = (const float*)d_in[16];
    const float* w7   = (const float*)d_in[17]; const float* b7   = (const float*)d_in[18];
    const float* w8   = (const float*)d_in[19]; const float* b8   = (const float*)d_in[20];
    const float* w9   = (const float*)d_in[21]; const float* b9   = (const float*)d_in[22];
    const float* w10  = (const float*)d_in[23]; const float* b10  = (const float*)d_in[24];
    const float* w11  = (const float*)d_in[25]; const float* b11  = (const float*)d_in[26];
    float* out = (float*)d_out;

    float* pool = nullptr;
    cudaGetSymbolAddress((void**)&pool, g_pool);

    const int BS = 256;
    const int N = 2;

    // s1 = conv3(x, 3->3)
    launch_conv<3, 0, 4>(x, 3, nullptr, 0, pool + O_S1, 3, w_s1, b_s1, 512, 512, N);
    maxpool_kernel<<<gs((long)N * 3 * 256 * 256, BS), BS>>>(pool + O_S1, pool + O_S2, 3, 256, 256, N);
    maxpool_kernel<<<gs((long)N * 3 * 128 * 128, BS), BS>>>(pool + O_S2, pool + O_S3, 3, 128, 128, N);
    maxpool_kernel<<<gs((long)N * 3 * 64 * 64, BS), BS>>>(pool + O_S3, pool + O_S4, 3, 64, 64, N);

    // multi concat
    upsample_kernel<<<gs((long)N * 3 * PX, BS), BS>>>(pool + O_S1, pool + O_MULTI + 0 * PX,
        3, 512, 512, 1, 3 * PX, 12 * PX, N);
    upsample_kernel<<<gs((long)N * 3 * PX, BS), BS>>>(pool + O_S2, pool + O_MULTI + 3 * PX,
        3, 256, 256, 2, 3 * (PX / 4), 12 * PX, N);
    upsample_kernel<<<gs((long)N * 3 * PX, BS), BS>>>(pool + O_S3, pool + O_MULTI + 6 * PX,
        3, 128, 128, 4, 3 * (PX / 16), 12 * PX, N);
    upsample_kernel<<<gs((long)N * 3 * PX, BS), BS>>>(pool + O_S4, pool + O_MULTI + 9 * PX,
        3, 64, 64, 8, 3 * (PX / 64), 12 * PX, N);

    // ms = conv3(multi, 12->16)
    launch_conv<3, 0, 8>(pool + O_MULTI, 12, nullptr, 0, pool + O_MS, 16, w_mc, b_mc, 512, 512, N);

    // c2 = relu(conv5(x, 3->16))
    launch_conv<5, 1, 8>(x, 3, nullptr, 0, pool + O_C2, 16, w2, b2, 512, 512, N);

    // encoder
    maxpool_kernel<<<gs((long)N * 16 * 256 * 256, BS), BS>>>(pool + O_C2, pool + O_C2P, 16, 256, 256, N);
    launch_conv<3, 1, 8>(pool + O_C2P, 16, nullptr, 0, pool + O_C3, 32, w3, b3, 256, 256, N);
    maxpool_kernel<<<gs((long)N * 32 * 128 * 128, BS), BS>>>(pool + O_C3, pool + O_C3P, 32, 128, 128, N);
    launch_conv<3, 1, 8>(pool + O_C3P, 32, nullptr, 0, pool + O_C4, 32, w4, b4, 128, 128, N);
    maxpool_kernel<<<gs((long)N * 32 * 64 * 64, BS), BS>>>(pool + O_C4, pool + O_C4P, 32, 64, 64, N);
    launch_conv<3, 1, 8>(pool + O_C4P, 32, nullptr, 0, pool + O_C5, 32, w5, b5, 64, 64, N);
    maxpool_kernel<<<gs((long)N * 32 * 32 * 32, BS), BS>>>(pool + O_C5, pool + O_C5P, 32, 32, 32, N);
    launch_conv<3, 1, 8>(pool + O_C5P, 32, nullptr, 0, pool + O_C6, 64, w6, b6, 32, 32, N);

    // c6re
    upsample_kernel<<<gs((long)N * 64 * 64 * 64, BS), BS>>>(pool + O_C6, pool + O_C6U,
        64, 32, 32, 2, 64L * 32 * 32, 64L * 64 * 64, N);
    launch_conv<3, 1, 8>(pool + O_C6U, 64, nullptr, 0, pool + O_C6S, 64, w6s, b6s, 64, 64, N);
    upsample_kernel<<<gs((long)N * 64 * 128 * 128, BS), BS>>>(pool + O_C6S, pool + O_C6RE,
        64, 64, 64, 2, 64L * 64 * 64, 64L * 128 * 128, N);

    // c7
    launch_conv<3, 1, 8>(pool + O_C6RE, 64, pool + O_C4, 32, pool + O_C7C, 32, w7, b7, 128, 128, N);
    upsample_kernel<<<gs((long)N * 32 * 256 * 256, BS), BS>>>(pool + O_C7C, pool + O_C7,
        32, 128, 128, 2, 32L * 128 * 128, 32L * 256 * 256, N);

    // c8
    launch_conv<3, 1, 8>(pool + O_C7, 32, pool + O_C3, 32, pool + O_C8C, 16, w8, b8, 256, 256, N);
    upsample_kernel<<<gs((long)N * 16 * 512 * 512, BS), BS>>>(pool + O_C8C, pool + O_C8,
        16, 256, 256, 2, 16L * 256 * 256, 16L * 512 * 512, N);

    // c9 = tanh(conv3(cat[c8, c2], 32->64))
    launch_conv<3, 2, 8>(pool + O_C8, 16, pool + O_C2, 16, pool + O_C9, 64, w9, b9, 512, 512, N);

    // scans
    hscan12_warp<<<gs(2L * 16 * 512 * 32, BS), BS>>>();
    vscan34_kernel<<<gs(2L * 16 * 512, BS), BS>>>();
    hscan56_warp<<<gs(2L * 16 * 512 * 32, BS), BS>>>();
    vscan78_kernel<<<gs(2L * 16 * 512, BS), BS>>>();

    // c10 = relu(conv3(elt_max, 16->64))
    launch_conv<3, 1, 8>(pool + O_ELT, 16, nullptr, 0, pool + O_C10, 64, w10, b10, 512, 512, N);

    // out = relu(conv3(c10, 64->3))
    launch_conv<3, 1, 4>(pool + O_C10, 64, nullptr, 0, out, 3, w11, b11, 512, 512, N);
}

// round 4
// speedup vs baseline: 3.2007x; 1.1523x over previous
#include <cuda_runtime.h>
#include <math.h>

// ---------------------------------------------------------------------------
// Scratch pool
// ---------------------------------------------------------------------------
static constexpr long PX = 512L * 512;

static constexpr long O_S1    = 0;
static constexpr long O_S2    = O_S1    + 6 * PX;
static constexpr long O_S3    = O_S2    + 6 * (PX / 4);
static constexpr long O_S4    = O_S3    + 6 * (PX / 16);
static constexpr long O_MULTI = O_S4    + 6 * (PX / 64);
static constexpr long O_MS    = O_MULTI + 24 * PX;
static constexpr long O_C2    = O_MS    + 32 * PX;
static constexpr long O_C2P   = O_C2    + 32 * PX;
static constexpr long O_C3    = O_C2P   + 32 * (PX / 4);
static constexpr long O_C3P   = O_C3    + 64 * (PX / 4);
static constexpr long O_C4    = O_C3P   + 64 * (PX / 16);
static constexpr long O_C4P   = O_C4    + 64 * (PX / 16);
static constexpr long O_C5    = O_C4P   + 64 * (PX / 64);
static constexpr long O_C5P   = O_C5    + 64 * (PX / 64);
static constexpr long O_C6    = O_C5P   + 64 * (PX / 256);
static constexpr long O_C6U   = O_C6    + 128 * (PX / 256);
static constexpr long O_C6S   = O_C6U   + 128 * (PX / 64);
static constexpr long O_C6RE  = O_C6S   + 128 * (PX / 64);
static constexpr long O_C7C   = O_C6RE  + 128 * (PX / 16);
static constexpr long O_C7    = O_C7C   + 64 * (PX / 16);
static constexpr long O_C8C   = O_C7    + 64 * (PX / 4);
static constexpr long O_C8    = O_C8C   + 32 * (PX / 4);
static constexpr long O_C9    = O_C8    + 32 * PX;
static constexpr long O_H3    = O_C9    + 128 * PX;
static constexpr long O_H4    = O_H3    + 32 * PX;
static constexpr long O_HM    = O_H4    + 32 * PX;
static constexpr long O_ELT   = O_HM    + 32 * PX;
static constexpr long O_C10   = O_ELT   + 32 * PX;
static constexpr long POOL_TOTAL = O_C10 + 128 * PX;

__device__ float g_pool[POOL_TOTAL];

// ---------------------------------------------------------------------------
// packed f32x2 helpers
// ---------------------------------------------------------------------------
typedef unsigned long long ull;

__device__ __forceinline__ ull pk2(float lo, float hi) {
    ull r;
    asm("mov.b64 %0, {%1, %2};" : "=l"(r) : "f"(lo), "f"(hi));
    return r;
}
__device__ __forceinline__ void upk2(float& lo, float& hi, ull v) {
    asm("mov.b64 {%0, %1}, %2;" : "=f"(lo), "=f"(hi) : "l"(v));
}
__device__ __forceinline__ ull fma2(ull a, ull b, ull c) {
    ull d;
    asm("fma.rn.f32x2 %0, %1, %2, %3;" : "=l"(d) : "l"(a), "l"(b), "l"(c));
    return d;
}

// ---------------------------------------------------------------------------
// Direct conv: XT x-outputs, CO couts (packed in f32x2 pairs) per thread.
// Weights staged in smem as [elem][co]; inputs packed {v,v} once per tap.
// ---------------------------------------------------------------------------
template <int K, int ACT, int CO, int XT>
__global__ __launch_bounds__(128)
void conv2d_pk(const float* __restrict__ srcA, int ca,
               const float* __restrict__ srcB, int cb,
               float* __restrict__ dst, int cout,
               const float* __restrict__ w,
               const float* __restrict__ bias,
               int H, int W, int N, int nblk)
{
    extern __shared__ float w_s[];   // [ctot*K*K][CO]
    const int ctot = ca + cb;
    const int coG = (cout + CO - 1) / CO;

    int blk  = blockIdx.x;
    int pblk = blk % nblk;
    int cog  = (blk / nblk) % coG;
    int n    = blk / (nblk * coG);
    int co0  = cog * CO;

    const int nw = ctot * K * K;
    for (int i = threadIdx.x; i < nw * CO; i += blockDim.x) {
        int e = i / CO;
        int j = i - e * CO;
        int co = co0 + j;
        w_s[i] = (co < cout) ? __ldg(w + (long)co * nw + e) : 0.0f;
    }
    __syncthreads();

    const int WXT = W / XT;
    int pos = pblk * blockDim.x + threadIdx.x;
    if (pos >= H * WXT) return;
    int y  = pos / WXT;
    int x0 = (pos % WXT) * XT;
    constexpr int P  = K / 2;
    constexpr int CP = CO / 2;
    constexpr int NV = K + XT - 1;

    ull acc[CP][XT];
#pragma unroll
    for (int cp = 0; cp < CP; ++cp) {
        float b0 = (co0 + 2 * cp     < cout) ? __ldg(bias + co0 + 2 * cp)     : 0.0f;
        float b1 = (co0 + 2 * cp + 1 < cout) ? __ldg(bias + co0 + 2 * cp + 1) : 0.0f;
        ull bp = pk2(b0, b1);
#pragma unroll
        for (int m = 0; m < XT; ++m) acc[cp][m] = bp;
    }

    bool xok[NV];
#pragma unroll
    for (int i = 0; i < NV; ++i) {
        int xx = x0 - P + i;
        xok[i] = (xx >= 0 && xx < W);
    }

    for (int ci = 0; ci < ctot; ++ci) {
        const float* plane = (ci < ca)
            ? srcA + ((long)n * ca + ci) * H * W
            : srcB + ((long)n * cb + (ci - ca)) * H * W;
        const float* ws = w_s + ci * (K * K * CO);

#pragma unroll
        for (int ky = 0; ky < K; ++ky) {
            int yy = y + ky - P;
            if (yy < 0 || yy >= H) continue;
            const float* r = plane + (long)yy * W + (x0 - P);
            ull pv[NV];
#pragma unroll
            for (int i = 0; i < NV; ++i) {
                float v = xok[i] ? __ldg(r + i) : 0.0f;
                pv[i] = pk2(v, v);
            }
#pragma unroll
            for (int kx = 0; kx < K; ++kx) {
                const float* we = ws + (ky * K + kx) * CO;
#pragma unroll
                for (int cp = 0; cp < CP; ++cp) {
                    ull wv = *reinterpret_cast<const ull*>(we + 2 * cp);
#pragma unroll
                    for (int m = 0; m < XT; ++m)
                        acc[cp][m] = fma2(wv, pv[kx + m], acc[cp][m]);
                }
            }
        }
    }

#pragma unroll
    for (int cp = 0; cp < CP; ++cp) {
        float o0[XT], o1[XT];
#pragma unroll
        for (int m = 0; m < XT; ++m) upk2(o0[m], o1[m], acc[cp][m]);
#pragma unroll
        for (int h = 0; h < 2; ++h) {
            int co = co0 + 2 * cp + h;
            if (co >= cout) break;
            float* ov = h ? o1 : o0;
#pragma unroll
            for (int m = 0; m < XT; ++m) {
                if (ACT == 1) ov[m] = fmaxf(ov[m], 0.f);
                else if (ACT == 2) ov[m] = tanhf(ov[m]);
            }
            long o = (((long)n * cout + co) * H + y) * W + x0;
#pragma unroll
            for (int q = 0; q < XT / 4; ++q)
                *reinterpret_cast<float4*>(dst + o + 4 * q) =
                    make_float4(ov[4 * q], ov[4 * q + 1], ov[4 * q + 2], ov[4 * q + 3]);
        }
    }
}

// ---------------------------------------------------------------------------
// 2x2 max pool
// ---------------------------------------------------------------------------
__global__ void maxpool_kernel(const float* __restrict__ src, float* __restrict__ dst,
                               int C, int Ho, int Wo, int N)
{
    long idx = (long)blockIdx.x * blockDim.x + threadIdx.x;
    long total = (long)N * C * Ho * Wo;
    if (idx >= total) return;
    int x = (int)(idx % Wo);  long t = idx / Wo;
    int y = (int)(t % Ho);    t /= Ho;
    int c = (int)(t % C);
    int n = (int)(t / C);
    int Hi = Ho * 2, Wi = Wo * 2;
    const float* p = src + (((long)n * C + c) * Hi + 2 * y) * Wi + 2 * x;
    dst[idx] = fmaxf(fmaxf(p[0], p[1]), fmaxf(p[Wi], p[Wi + 1]));
}

// ---------------------------------------------------------------------------
// Bilinear upsample
// ---------------------------------------------------------------------------
__global__ void upsample_kernel(const float* __restrict__ src, float* __restrict__ dst,
                                int C, int Hs, int Ws, int scale,
                                long sBS, long dBS, int N)
{
    int Hd = Hs * scale, Wd = Ws * scale;
    long idx = (long)blockIdx.x * blockDim.x + threadIdx.x;
    long total = (long)N * C * Hd * Wd;
    if (idx >= total) return;
    int x = (int)(idx % Wd);  long t = idx / Wd;
    int y = (int)(t % Hd);    t /= Hd;
    int c = (int)(t % C);
    int n = (int)(t / C);

    float inv = 1.0f / (float)scale;
    float fy = (y + 0.5f) * inv - 0.5f;
    float fx = (x + 0.5f) * inv - 0.5f;
    int y0 = (int)floorf(fy);
    int x0 = (int)floorf(fx);
    float wy = fy - (float)y0;
    float wx = fx - (float)x0;
    int y0c = min(max(y0, 0), Hs - 1);
    int y1c = min(max(y0 + 1, 0), Hs - 1);
    int x0c = min(max(x0, 0), Ws - 1);
    int x1c = min(max(x0 + 1, 0), Ws - 1);

    const float* p = src + n * sBS + (long)c * Hs * Ws;
    float v00 = p[(long)y0c * Ws + x0c];
    float v01 = p[(long)y0c * Ws + x1c];
    float v10 = p[(long)y1c * Ws + x0c];
    float v11 = p[(long)y1c * Ws + x1c];
    float v = (1.f - wy) * ((1.f - wx) * v00 + wx * v01)
            +        wy  * ((1.f - wx) * v10 + wx * v11);

    dst[n * dBS + ((long)c * Hd + y) * Wd + x] = v;
}

// ---------------------------------------------------------------------------
// Warp affine scan helper
// ---------------------------------------------------------------------------
__device__ __forceinline__ float warp_affine_prefix(float& A, float& B, int lane)
{
#pragma unroll
    for (int d = 1; d < 32; d <<= 1) {
        float Ap = __shfl_up_sync(0xffffffffu, A, d);
        float Bp = __shfl_up_sync(0xffffffffu, B, d);
        if (lane >= d) { B = fmaf(A, Bp, B); A *= Ap; }
    }
    float yin = __shfl_up_sync(0xffffffffu, B, 1);
    return (lane == 0) ? 0.0f : yin;
}

// ---------------------------------------------------------------------------
// Fused horizontal scans: h1,h2 (gx1 over ms fwd/rev) then h5,h6 (gx2 over
// h1 fwd / h2 rev) -> hm = max(h5,h6). All in registers; h1/h2 never hit gmem.
// One warp per (n,c,y) row; grid exact (no guards; shuffles need full warps).
// ---------------------------------------------------------------------------
__global__ __launch_bounds__(256) void hscan_fused()
{
    int gw = (blockIdx.x * blockDim.x + threadIdx.x) >> 5;   // 0..16383
    int lane = threadIdx.x & 31;
    int y = gw % 512;  int t = gw / 512;
    int c = t % 16;    int n = t / 16;
    long rowc = ((long)(n * 16 + c) * 512 + y) * 512;
    const float* a1 = g_pool + O_C9 + ((long)(n * 64 + c)      * 512 + y) * 512;
    const float* a2 = g_pool + O_C9 + ((long)(n * 64 + 32 + c) * 512 + y) * 512;
    const float* u  = g_pool + O_MS + rowc;
    float* hm = g_pool + O_HM + rowc;
    int x0 = lane * 16;
    int mlane = 31 - lane;

    float a1v[16], ufv[16], h1v[16], h2v[16];
#pragma unroll
    for (int k = 0; k < 16; ++k) { a1v[k] = a1[x0 + k]; ufv[k] = u[x0 + k]; }

    // h1 = scan(gx1, u)
    float A = 1.f, B = 0.f;
#pragma unroll
    for (int k = 0; k < 16; ++k) {
        float av = a1v[k];
        B = fmaf(av, B, (1.f - av) * ufv[k]);
        A *= av;
    }
    float yv = warp_affine_prefix(A, B, lane);
#pragma unroll
    for (int k = 0; k < 16; ++k) {
        float av = a1v[k];
        yv = fmaf(av, yv, (1.f - av) * ufv[k]);
        h1v[k] = yv;
    }

    // h2 = scan(gx1, u reversed): u2[k] = u[511 - (x0+k)] via mirror shuffle
    float u2v[16];
#pragma unroll
    for (int k = 0; k < 16; ++k)
        u2v[k] = __shfl_sync(0xffffffffu, ufv[15 - k], mlane);
    A = 1.f; B = 0.f;
#pragma unroll
    for (int k = 0; k < 16; ++k) {
        float av = a1v[k];
        B = fmaf(av, B, (1.f - av) * u2v[k]);
        A *= av;
    }
    yv = warp_affine_prefix(A, B, lane);
#pragma unroll
    for (int k = 0; k < 16; ++k) {
        float av = a1v[k];
        yv = fmaf(av, yv, (1.f - av) * u2v[k]);
        h2v[k] = yv;
    }

    // reload gate gx2 into a1v
#pragma unroll
    for (int k = 0; k < 16; ++k) a1v[k] = a2[x0 + k];

    // h5 = scan(gx2, h1) -> store into h1v
    A = 1.f; B = 0.f;
#pragma unroll
    for (int k = 0; k < 16; ++k) {
        float av = a1v[k];
        B = fmaf(av, B, (1.f - av) * h1v[k]);
        A *= av;
    }
    yv = warp_affine_prefix(A, B, lane);
#pragma unroll
    for (int k = 0; k < 16; ++k) {
        float av = a1v[k];
        yv = fmaf(av, yv, (1.f - av) * h1v[k]);
        h1v[k] = yv;   // = h5
    }

    // h6 = scan(gx2, h2 reversed)
    float u6v[16];
#pragma unroll
    for (int k = 0; k < 16; ++k)
        u6v[k] = __shfl_sync(0xffffffffu, h2v[15 - k], mlane);
    A = 1.f; B = 0.f;
#pragma unroll
    for (int k = 0; k < 16; ++k) {
        float av = a1v[k];
        B = fmaf(av, B, (1.f - av) * u6v[k]);
        A *= av;
    }
    yv = warp_affine_prefix(A, B, lane);
#pragma unroll
    for (int k = 0; k < 16; ++k) {
        float av = a1v[k];
        yv = fmaf(av, yv, (1.f - av) * u6v[k]);
        hm[x0 + k] = fmaxf(h1v[k], yv);
    }
}

// ---------------------------------------------------------------------------
// Block-parallel vertical scans: 256 threads = 8 y-groups x 32 x-columns.
// Two-level: per-group affine aggregate, smem cross-group scan, replay.
// ---------------------------------------------------------------------------
__global__ __launch_bounds__(256) void vscan34_blk()
{
    int blk = blockIdx.x;                   // n*16*16 + c*16 + strip
    int strip = blk & 15;  int t = blk >> 4;
    int c = t & 15;        int n = t >> 4;
    int lx = threadIdx.x & 31;
    int g  = threadIdx.x >> 5;
    int x = strip * 32 + lx;

    const float* gx1 = g_pool + O_C9 + (long)(n * 64 + c)      * PX;
    const float* gy1 = g_pool + O_C9 + (long)(n * 64 + 16 + c) * PX;
    const float* u   = g_pool + O_MS + (long)(n * 16 + c) * PX;
    float* h3 = g_pool + O_H3 + (long)(n * 16 + c) * PX;
    float* h4 = g_pool + O_H4 + (long)(n * 16 + c) * PX;

    __shared__ float sA[8][33], s3[8][33], s4[8][33];
    int y0 = g << 6;

    float A = 1.f, B3 = 0.f, B4 = 0.f;
    for (int i = 0; i < 64; ++i) {
        int y = y0 + i;
        float av = (y == 0) ? gy1[x] : gx1[(long)y * 512 + x];
        float om = 1.f - av;
        B3 = fmaf(av, B3, om * u[(long)y * 512 + x]);
        B4 = fmaf(av, B4, om * u[(long)(511 - y) * 512 + x]);
        A *= av;
    }
    sA[g][lx] = A; s3[g][lx] = B3; s4[g][lx] = B4;
    __syncthreads();
    if (g == 0) {
        float p3 = 0.f, p4 = 0.f;
        for (int gg = 0; gg < 8; ++gg) {
            float a_ = sA[gg][lx], b3 = s3[gg][lx], b4 = s4[gg][lx];
            s3[gg][lx] = p3; s4[gg][lx] = p4;
            p3 = fmaf(a_, p3, b3); p4 = fmaf(a_, p4, b4);
        }
    }
    __syncthreads();
    float y3 = s3[g][lx], y4 = s4[g][lx];
    for (int i = 0; i < 64; ++i) {
        int y = y0 + i;
        float av = (y == 0) ? gy1[x] : gx1[(long)y * 512 + x];
        float om = 1.f - av;
        y3 = fmaf(av, y3, om * u[(long)y * 512 + x]);
        h3[(long)y * 512 + x] = y3;
        y4 = fmaf(av, y4, om * u[(long)(511 - y) * 512 + x]);
        h4[(long)y * 512 + x] = y4;
    }
}

__global__ __launch_bounds__(256) void vscan78_blk()
{
    int blk = blockIdx.x;
    int strip = blk & 15;  int t = blk >> 4;
    int c = t & 15;        int n = t >> 4;
    int lx = threadIdx.x & 31;
    int g  = threadIdx.x >> 5;
    int x = strip * 32 + lx;

    const float* a  = g_pool + O_C9 + (long)(n * 64 + 48 + c) * PX;
    const float* h3 = g_pool + O_H3 + (long)(n * 16 + c) * PX;
    const float* h4 = g_pool + O_H4 + (long)(n * 16 + c) * PX;
    const float* hm = g_pool + O_HM + (long)(n * 16 + c) * PX;
    float* elt = g_pool + O_ELT + (long)(n * 16 + c) * PX;

    __shared__ float sA[8][33], s7[8][33], s8[8][33];
    int y0 = g << 6;

    float A = 1.f, B7 = 0.f, B8 = 0.f;
    for (int i = 0; i < 64; ++i) {
        int y = y0 + i;
        float av = a[(long)y * 512 + x];
        float om = 1.f - av;
        B7 = fmaf(av, B7, om * h3[(long)y * 512 + x]);
        B8 = fmaf(av, B8, om * h4[(long)(511 - y) * 512 + x]);
        A *= av;
    }
    sA[g][lx] = A; s7[g][lx] = B7; s8[g][lx] = B8;
    __syncthreads();
    if (g == 0) {
        float p7 = 0.f, p8 = 0.f;
        for (int gg = 0; gg < 8; ++gg) {
            float a_ = sA[gg][lx], b7 = s7[gg][lx], b8 = s8[gg][lx];
            s7[gg][lx] = p7; s8[gg][lx] = p8;
            p7 = fmaf(a_, p7, b7); p8 = fmaf(a_, p8, b8);
        }
    }
    __syncthreads();
    float y7 = s7[g][lx], y8 = s8[g][lx];
    for (int i = 0; i < 64; ++i) {
        int y = y0 + i;
        float av = a[(long)y * 512 + x];
        float om = 1.f - av;
        y7 = fmaf(av, y7, om * h3[(long)y * 512 + x]);
        y8 = fmaf(av, y8, om * h4[(long)(511 - y) * 512 + x]);
        elt[(long)y * 512 + x] = fmaxf(hm[(long)y * 512 + x], fmaxf(y7, y8));
    }
}

// ---------------------------------------------------------------------------
// Launch helpers
// ---------------------------------------------------------------------------
static inline int gs(long total, int bs) { return (int)((total + bs - 1) / bs); }

template <int K, int ACT, int CO, int XT>
static void launch_conv(const float* srcA, int ca, const float* srcB, int cb,
                        float* dst, int cout, const float* w, const float* b,
                        int H, int W, int N)
{
    const int BT = 128;
    int WXT = W / XT;
    int nblk = (H * WXT + BT - 1) / BT;
    int coG = (cout + CO - 1) / CO;
    int blocks = N * coG * nblk;
    int smem = (ca + cb) * K * K * CO * (int)sizeof(float);
    conv2d_pk<K, ACT, CO, XT><<<blocks, BT, smem>>>(srcA, ca, srcB, cb, dst, cout, w, b, H, W, N, nblk);
}

extern "C" void kernel_launch(void* const* d_in, const int* in_sizes, int n_in,
                              void* d_out, int out_size)
{
    const float* x    = (const float*)d_in[0];
    const float* w_s1 = (const float*)d_in[1];  const float* b_s1 = (const float*)d_in[2];
    const float* w_mc = (const float*)d_in[3];  const float* b_mc = (const float*)d_in[4];
    const float* w2   = (const float*)d_in[5];  const float* b2   = (const float*)d_in[6];
    const float* w3   = (const float*)d_in[7];  const float* b3   = (const float*)d_in[8];
    const float* w4   = (const float*)d_in[9];  const float* b4   = (const float*)d_in[10];
    const float* w5   = (const float*)d_in[11]; const float* b5   = (const float*)d_in[12];
    const float* w6   = (const float*)d_in[13]; const float* b6   = (const float*)d_in[14];
    const float* w6s  = (const float*)d_in[15]; const float* b6s  = (const float*)d_in[16];
    const float* w7   = (const float*)d_in[17]; const float* b7   = (const float*)d_in[18];
    const float* w8   = (const float*)d_in[19]; const float* b8   = (const float*)d_in[20];
    const float* w9   = (const float*)d_in[21]; const float* b9   = (const float*)d_in[22];
    const float* w10  = (const float*)d_in[23]; const float* b10  = (const float*)d_in[24];
    const float* w11  = (const float*)d_in[25]; const float* b11  = (const float*)d_in[26];
    float* out = (float*)d_out;

    float* pool = nullptr;
    cudaGetSymbolAddress((void**)&pool, g_pool);

    const int BS = 256;
    const int N = 2;

    // s1 = conv3(x, 3->3)
    launch_conv<3, 0, 4, 8>(x, 3, nullptr, 0, pool + O_S1, 3, w_s1, b_s1, 512, 512, N);
    maxpool_kernel<<<gs((long)N * 3 * 256 * 256, BS), BS>>>(pool + O_S1, pool + O_S2, 3, 256, 256, N);
    maxpool_kernel<<<gs((long)N * 3 * 128 * 128, BS), BS>>>(pool + O_S2, pool + O_S3, 3, 128, 128, N);
    maxpool_kernel<<<gs((long)N * 3 * 64 * 64, BS), BS>>>(pool + O_S3, pool + O_S4, 3, 64, 64, N);

    // multi concat
    upsample_kernel<<<gs((long)N * 3 * PX, BS), BS>>>(pool + O_S1, pool + O_MULTI + 0 * PX,
        3, 512, 512, 1, 3 * PX, 12 * PX, N);
    upsample_kernel<<<gs((long)N * 3 * PX, BS), BS>>>(pool + O_S2, pool + O_MULTI + 3 * PX,
        3, 256, 256, 2, 3 * (PX / 4), 12 * PX, N);
    upsample_kernel<<<gs((long)N * 3 * PX, BS), BS>>>(pool + O_S3, pool + O_MULTI + 6 * PX,
        3, 128, 128, 4, 3 * (PX / 16), 12 * PX, N);
    upsample_kernel<<<gs((long)N * 3 * PX, BS), BS>>>(pool + O_S4, pool + O_MULTI + 9 * PX,
        3, 64, 64, 8, 3 * (PX / 64), 12 * PX, N);

    // ms = conv3(multi, 12->16)
    launch_conv<3, 0, 8, 8>(pool + O_MULTI, 12, nullptr, 0, pool + O_MS, 16, w_mc, b_mc, 512, 512, N);

    // c2 = relu(conv5(x, 3->16))
    launch_conv<5, 1, 8, 4>(x, 3, nullptr, 0, pool + O_C2, 16, w2, b2, 512, 512, N);

    // encoder
    maxpool_kernel<<<gs((long)N * 16 * 256 * 256, BS), BS>>>(pool + O_C2, pool + O_C2P, 16, 256, 256, N);
    launch_conv<3, 1, 8, 8>(pool + O_C2P, 16, nullptr, 0, pool + O_C3, 32, w3, b3, 256, 256, N);
    maxpool_kernel<<<gs((long)N * 32 * 128 * 128, BS), BS>>>(pool + O_C3, pool + O_C3P, 32, 128, 128, N);
    launch_conv<3, 1, 8, 8>(pool + O_C3P, 32, nullptr, 0, pool + O_C4, 32, w4, b4, 128, 128, N);
    maxpool_kernel<<<gs((long)N * 32 * 64 * 64, BS), BS>>>(pool + O_C4, pool + O_C4P, 32, 64, 64, N);
    launch_conv<3, 1, 8, 4>(pool + O_C4P, 32, nullptr, 0, pool + O_C5, 32, w5, b5, 64, 64, N);
    maxpool_kernel<<<gs((long)N * 32 * 32 * 32, BS), BS>>>(pool + O_C5, pool + O_C5P, 32, 32, 32, N);
    launch_conv<3, 1, 8, 4>(pool + O_C5P, 32, nullptr, 0, pool + O_C6, 64, w6, b6, 32, 32, N);

    // c6re
    upsample_kernel<<<gs((long)N * 64 * 64 * 64, BS), BS>>>(pool + O_C6, pool + O_C6U,
        64, 32, 32, 2, 64L * 32 * 32, 64L * 64 * 64, N);
    launch_conv<3, 1, 8, 4>(pool + O_C6U, 64, nullptr, 0, pool + O_C6S, 64, w6s, b6s, 64, 64, N);
    upsample_kernel<<<gs((long)N * 64 * 128 * 128, BS), BS>>>(pool + O_C6S, pool + O_C6RE,
        64, 64, 64, 2, 64L * 64 * 64, 64L * 128 * 128, N);

    // c7
    launch_conv<3, 1, 8, 8>(pool + O_C6RE, 64, pool + O_C4, 32, pool + O_C7C, 32, w7, b7, 128, 128, N);
    upsample_kernel<<<gs((long)N * 32 * 256 * 256, BS), BS>>>(pool + O_C7C, pool + O_C7,
        32, 128, 128, 2, 32L * 128 * 128, 32L * 256 * 256, N);

    // c8
    launch_conv<3, 1, 8, 8>(pool + O_C7, 32, pool + O_C3, 32, pool + O_C8C, 16, w8, b8, 256, 256, N);
    upsample_kernel<<<gs((long)N * 16 * 512 * 512, BS), BS>>>(pool + O_C8C, pool + O_C8,
        16, 256, 256, 2, 16L * 256 * 256, 16L * 512 * 512, N);

    // c9 = tanh(conv3(cat[c8, c2], 32->64))
    launch_conv<3, 2, 8, 8>(pool + O_C8, 16, pool + O_C2, 16, pool + O_C9, 64, w9, b9, 512, 512, N);

    // scans
    hscan_fused<<<2048, 256>>>();
    vscan34_blk<<<512, 256>>>();
    vscan78_blk<<<512, 256>>>();

    // c10 = relu(conv3(elt_max, 16->64))
    launch_conv<3, 1, 8, 8>(pool + O_ELT, 16, nullptr, 0, pool + O_C10, 64, w10, b10, 512, 512, N);

    // out = relu(conv3(c10, 64->3))
    launch_conv<3, 1, 4, 8>(pool + O_C10, 64, nullptr, 0, out, 3, w11, b11, 512, 512, N);
}